// round 9
// baseline (speedup 1.0000x reference)
#include <cuda_runtime.h>
#include <cuda_bf16.h>
#include <cstdint>

#define B_SZ  2
#define S_LEN 2048
#define E_DIM 256
#define TQ    32          // q rows per attention block
#define KR    288         // k rows per block window
#define SST   292         // Ssm f32 row stride
#define QSA   264         // Q smem halfword stride (528B rows)
#define PST   296         // P smem halfword stride (592B rows)
#define KCH   40          // K/V chunk halfword stride (80B rows)

// attn smem layout (bytes)
#define R2    37376       // Q (later P) region; R1 = S at 0
#define R3    75264       // K/V triple buffers
#define BUFB  46080       // bytes per buffer (hi+lo)
#define HLO   23040       // lo half offset within buffer
#define ATTN_SMEM (R3 + 3 * BUFB)   // 213504

// qkv gemm smem: 3 stages x (Ah,Al,Bh,Bl each 128x40 bf16 = 10240B)
#define STG   40960
#define QKV_SMEM (3 * STG)          // 122880

// pre-split inputs
__device__ __nv_bfloat16 g_xh[B_SZ * S_LEN * E_DIM];
__device__ __nv_bfloat16 g_xl[B_SZ * S_LEN * E_DIM];
__device__ __nv_bfloat16 g_wh[3 * E_DIM * E_DIM];
__device__ __nv_bfloat16 g_wl[3 * E_DIM * E_DIM];
// bf16 hi/lo q,k,v
__device__ __nv_bfloat16 g_qh[B_SZ * S_LEN * E_DIM];
__device__ __nv_bfloat16 g_ql[B_SZ * S_LEN * E_DIM];
__device__ __nv_bfloat16 g_kh[B_SZ * S_LEN * E_DIM];
__device__ __nv_bfloat16 g_kl[B_SZ * S_LEN * E_DIM];
__device__ __nv_bfloat16 g_vh[B_SZ * S_LEN * E_DIM];
__device__ __nv_bfloat16 g_vl[B_SZ * S_LEN * E_DIM];

// ---------------------------------------------------------------------------
// PTX helpers
// ---------------------------------------------------------------------------
__device__ __forceinline__ uint32_t smem_u32(const void* p) {
    uint32_t a;
    asm("{ .reg .u64 t; cvta.to.shared.u64 t, %1; cvt.u32.u64 %0, t; }"
        : "=r"(a) : "l"(p));
    return a;
}

__device__ __forceinline__ void ldsm_x4(uint32_t& r0, uint32_t& r1,
                                        uint32_t& r2, uint32_t& r3, uint32_t a) {
    asm volatile("ldmatrix.sync.aligned.m8n8.x4.shared.b16 {%0,%1,%2,%3}, [%4];"
                 : "=r"(r0), "=r"(r1), "=r"(r2), "=r"(r3) : "r"(a));
}

__device__ __forceinline__ void ldsm_x2(uint32_t& r0, uint32_t& r1, uint32_t a) {
    asm volatile("ldmatrix.sync.aligned.m8n8.x2.shared.b16 {%0,%1}, [%2];"
                 : "=r"(r0), "=r"(r1) : "r"(a));
}

__device__ __forceinline__ void ldsm_x2_t(uint32_t& r0, uint32_t& r1, uint32_t a) {
    asm volatile("ldmatrix.sync.aligned.m8n8.x2.trans.shared.b16 {%0,%1}, [%2];"
                 : "=r"(r0), "=r"(r1) : "r"(a));
}

__device__ __forceinline__ void mma_bf16(float* d, const uint32_t* a,
                                         const uint32_t* b) {
    asm volatile(
        "mma.sync.aligned.m16n8k16.row.col.f32.bf16.bf16.f32 "
        "{%0,%1,%2,%3}, {%4,%5,%6,%7}, {%8,%9}, {%0,%1,%2,%3};"
        : "+f"(d[0]), "+f"(d[1]), "+f"(d[2]), "+f"(d[3])
        : "r"(a[0]), "r"(a[1]), "r"(a[2]), "r"(a[3]), "r"(b[0]), "r"(b[1]));
}

__device__ __forceinline__ void bf16_split(float x, __nv_bfloat16& hi,
                                           __nv_bfloat16& lo) {
    hi = __float2bfloat16_rn(x);
    lo = __float2bfloat16_rn(x - __bfloat162float(hi));
}

__device__ __forceinline__ void cp16(uint32_t dst, const void* src, int srcsize) {
    asm volatile("cp.async.cg.shared.global [%0], [%1], 16, %2;"
                 :: "r"(dst), "l"(src), "r"(srcsize) : "memory");
}
#define CP_COMMIT() asm volatile("cp.async.commit_group;" ::: "memory")
#define CP_WAIT0()  asm volatile("cp.async.wait_group 0;" ::: "memory")
#define CP_WAIT1()  asm volatile("cp.async.wait_group 1;" ::: "memory")
#define CP_WAIT2()  asm volatile("cp.async.wait_group 2;" ::: "memory")

// ---------------------------------------------------------------------------
// Kernel 0: split x and W into bf16 hi/lo (once).
// ---------------------------------------------------------------------------
#define X4 262144   // 4096*256/4
#define W4 16384    // 256*256/4 per matrix

__global__ __launch_bounds__(256) void prep_split_kernel(
    const float* __restrict__ x, const float* __restrict__ Wq,
    const float* __restrict__ Wk, const float* __restrict__ Wv)
{
    int idx = blockIdx.x * 256 + threadIdx.x;
    if (idx >= X4 + 3 * W4) return;
    const float* src;
    __nv_bfloat16 *dh, *dl;
    if (idx < X4) {
        src = x + (size_t)idx * 4;
        dh = g_xh + (size_t)idx * 4;
        dl = g_xl + (size_t)idx * 4;
    } else {
        int w = idx - X4;
        int z = w / W4, o = w % W4;
        const float* Wp = (z == 0) ? Wq : (z == 1) ? Wk : Wv;
        src = Wp + (size_t)o * 4;
        dh = g_wh + (size_t)z * 65536 + (size_t)o * 4;
        dl = g_wl + (size_t)z * 65536 + (size_t)o * 4;
    }
    float4 v = *(const float4*)src;
    __nv_bfloat16 h0, l0, h1, l1, h2, l2, h3, l3;
    bf16_split(v.x, h0, l0); bf16_split(v.y, h1, l1);
    bf16_split(v.z, h2, l2); bf16_split(v.w, h3, l3);
    ((__nv_bfloat162*)dh)[0] = __nv_bfloat162(h0, h1);
    ((__nv_bfloat162*)dh)[1] = __nv_bfloat162(h2, h3);
    ((__nv_bfloat162*)dl)[0] = __nv_bfloat162(l0, l1);
    ((__nv_bfloat162*)dl)[1] = __nv_bfloat162(l2, l3);
}

// ---------------------------------------------------------------------------
// Kernel 1: QKV GEMM on pre-split operands, cp.async 3-stage pipeline.
// C = Xs @ Ws^T + b, CTA tile M=128 N=128 K=256 (BK=32), grid (32,2,3).
// Stage layout: Ah@0, Al@10240, Bh@20480, Bl@30720 (rows stride 80B).
// ---------------------------------------------------------------------------
__device__ __forceinline__ void issue_ab_chunk(
    uint32_t stage_base, int m0, int n0, int z, int kc, int tid)
{
    #pragma unroll
    for (int p = 0; p < 8; p++) {
        int idx  = tid + p * 256;          // 0..2047
        int isB  = idx >> 10;
        int u    = idx & 1023;
        int isLo = u >> 9;
        int u2   = u & 511;
        int r    = u2 >> 2;                // 0..127
        int seg  = u2 & 3;                 // 16B segment
        const __nv_bfloat16* src;
        if (isB)
            src = (isLo ? g_wl : g_wh) + (size_t)z * 65536 +
                  (size_t)(n0 + r) * 256 + kc + seg * 8;
        else
            src = (isLo ? g_xl : g_xh) + (size_t)(m0 + r) * 256 + kc + seg * 8;
        uint32_t dst = stage_base + isB * 20480 + isLo * 10240 + r * 80 + seg * 16;
        cp16(dst, src, 16);
    }
}

__global__ __launch_bounds__(256) void qkv_gemm_kernel(
    const float* __restrict__ bq, const float* __restrict__ bk,
    const float* __restrict__ bv)
{
    extern __shared__ char smem[];
    const uint32_t sb = smem_u32(smem);

    const int z = blockIdx.z;
    const float* __restrict__ bias = (z == 0) ? bq : (z == 1) ? bk : bv;
    __nv_bfloat16* __restrict__ Ch = (z == 0) ? g_qh : (z == 1) ? g_kh : g_vh;
    __nv_bfloat16* __restrict__ Cl = (z == 0) ? g_ql : (z == 1) ? g_kl : g_vl;

    const int m0 = blockIdx.x * 128;
    const int n0 = blockIdx.y * 128;
    const int tid  = threadIdx.x;
    const int wid  = tid >> 5;
    const int lane = tid & 31;
    const int wm   = wid >> 2;
    const int wn   = wid & 3;

    float acc[4][4][4];
    #pragma unroll
    for (int i = 0; i < 4; i++)
        #pragma unroll
        for (int j = 0; j < 4; j++)
            #pragma unroll
            for (int e = 0; e < 4; e++) acc[i][j][e] = 0.f;

    const int aRow = (lane & 15);
    const int aCol = (lane >> 4) * 8;
    const int l15  = lane & 15;
    const int bRow = (l15 & 7);
    const int bCol = (l15 >> 3) * 8;

    // prologue: chunks 0..2 into stages 0..2
    issue_ab_chunk(sb, m0, n0, z, 0, tid);            CP_COMMIT();
    issue_ab_chunk(sb + STG, m0, n0, z, 32, tid);     CP_COMMIT();
    issue_ab_chunk(sb + 2 * STG, m0, n0, z, 64, tid); CP_COMMIT();

    for (int c = 0; c < 8; c++) {
        if (c == 0) CP_WAIT2(); else if (c <= 6) CP_WAIT1(); else CP_WAIT0();
        __syncthreads();
        if (c >= 1 && c <= 5) {
            issue_ab_chunk(sb + ((c + 2) % 3) * STG, m0, n0, z, (c + 2) * 32, tid);
            CP_COMMIT();
        }

        const uint32_t base = sb + (c % 3) * STG;
        #pragma unroll
        for (int kk = 0; kk < 32; kk += 16) {
            uint32_t ah[4][4], al[4][4], bh[4][2], bl[4][2];
            #pragma unroll
            for (int mi = 0; mi < 4; mi++) {
                uint32_t off = (uint32_t)((wm * 64 + mi * 16 + aRow) * 40 +
                                          kk + aCol) * 2;
                ldsm_x4(ah[mi][0], ah[mi][1], ah[mi][2], ah[mi][3], base + off);
                ldsm_x4(al[mi][0], al[mi][1], al[mi][2], al[mi][3],
                        base + 10240 + off);
            }
            #pragma unroll
            for (int nj = 0; nj < 4; nj++) {
                uint32_t off = (uint32_t)((wn * 32 + nj * 8 + bRow) * 40 +
                                          kk + bCol) * 2;
                ldsm_x2(bh[nj][0], bh[nj][1], base + 20480 + off);
                ldsm_x2(bl[nj][0], bl[nj][1], base + 30720 + off);
            }
            #pragma unroll
            for (int mi = 0; mi < 4; mi++)
                #pragma unroll
                for (int nj = 0; nj < 4; nj++) {
                    mma_bf16(acc[mi][nj], ah[mi], bh[nj]);
                    mma_bf16(acc[mi][nj], ah[mi], bl[nj]);
                    mma_bf16(acc[mi][nj], al[mi], bh[nj]);
                }
        }
    }

    // epilogue: add bias, split to bf16 hi/lo, store
    #pragma unroll
    for (int mi = 0; mi < 4; mi++) {
        int r0 = m0 + wm * 64 + mi * 16 + (lane >> 2);
        #pragma unroll
        for (int nj = 0; nj < 4; nj++) {
            int col = n0 + wn * 32 + nj * 8 + (lane & 3) * 2;
            float2 bv2 = *(const float2*)&bias[col];
            #pragma unroll
            for (int h = 0; h < 2; h++) {
                int row = r0 + h * 8;
                float cx = acc[mi][nj][h * 2 + 0] + bv2.x;
                float cy = acc[mi][nj][h * 2 + 1] + bv2.y;
                __nv_bfloat16 hx, lx, hy, ly;
                bf16_split(cx, hx, lx);
                bf16_split(cy, hy, ly);
                *(__nv_bfloat162*)&Ch[(size_t)row * 256 + col] = __nv_bfloat162(hx, hy);
                *(__nv_bfloat162*)&Cl[(size_t)row * 256 + col] = __nv_bfloat162(lx, ly);
            }
        }
    }
}

// ---------------------------------------------------------------------------
// attn helpers: async chunk issuance
// ---------------------------------------------------------------------------
__device__ __forceinline__ void issue_kv_chunk(
    uint32_t dst_base, const __nv_bfloat16* __restrict__ hi,
    const __nv_bfloat16* __restrict__ lo, int s0, int colbase, int tid)
{
    #pragma unroll
    for (int p = 0; p < 9; p++) {
        int idx  = tid + p * 256;              // 0..2303
        int half = idx >= 1152;
        int u    = half ? idx - 1152 : idx;
        int r    = u >> 2;                     // 0..287
        int seg  = u & 3;                      // 16B segment
        int g    = s0 - 128 + r;
        bool ok  = (unsigned)g < S_LEN;
        const __nv_bfloat16* src =
            (half ? lo : hi) + (size_t)(ok ? g : 0) * 256 + colbase + seg * 8;
        uint32_t dst = dst_base + half * HLO + r * 80 + seg * 16;
        cp16(dst, src, ok ? 16 : 0);
    }
}

// ---------------------------------------------------------------------------
// Kernel 2: banded attention, tensor-core + cp.async pipeline, 1 sync/chunk.
// Block = 32 q rows of one batch, 256 threads, 8 warps (2m x 4n).
// ---------------------------------------------------------------------------
__global__ __launch_bounds__(256) void attn_tc_kernel(float* __restrict__ out)
{
    extern __shared__ char smem[];
    const uint32_t sb = smem_u32(smem);
    float* Ssm = (float*)smem;
    __nv_bfloat16* Ph = (__nv_bfloat16*)(smem + R2);
    __nv_bfloat16* Pl = (__nv_bfloat16*)(smem + R2 + 18944);

    const int b    = blockIdx.y;
    const int s0   = blockIdx.x * TQ;
    const int tid  = threadIdx.x;
    const int wid  = tid >> 5;
    const int lane = tid & 31;
    const int wm   = wid >> 2;       // 0..1 -> 16-row half
    const int wn   = wid & 3;        // 0..3

    const size_t boff = (size_t)b * S_LEN * E_DIM;
    const __nv_bfloat16* __restrict__ qh = g_qh + boff;
    const __nv_bfloat16* __restrict__ ql = g_ql + boff;
    const __nv_bfloat16* __restrict__ kh = g_kh + boff;
    const __nv_bfloat16* __restrict__ kl = g_kl + boff;
    const __nv_bfloat16* __restrict__ vh = g_vh + boff;
    const __nv_bfloat16* __restrict__ vl = g_vl + boff;

    const int aRow  = lane & 15;
    const int aCol  = (lane >> 4) * 8;
    const int bRowE = (lane & 7) + ((lane >> 4) << 3);
    const int bColE = ((lane >> 3) & 1) * 8;

    // ---- prologue: async Q (group 0 with K0) + K chunks 0..2 ----
    #pragma unroll
    for (int p = 0; p < 8; p++) {
        int idx  = tid + p * 256;              // 0..2047
        int half = idx >> 10;
        int rem  = idx & 1023;
        int r    = rem >> 5;                   // 0..31
        int seg  = rem & 31;
        const __nv_bfloat16* src =
            (half ? ql : qh) + (size_t)(s0 + r) * 256 + seg * 8;
        cp16(sb + R2 + half * 16896 + r * 528 + seg * 16, src, 16);
    }
    issue_kv_chunk(sb + R3, kh, kl, s0, 0, tid);             CP_COMMIT();
    issue_kv_chunk(sb + R3 + BUFB, kh, kl, s0, 32, tid);     CP_COMMIT();
    issue_kv_chunk(sb + R3 + 2 * BUFB, kh, kl, s0, 64, tid); CP_COMMIT();

    // ---- Phase 1: energy S[32][288] = Q @ K^T, 8 chunks, 1 sync/chunk ----
    float acc[9][4];
    #pragma unroll
    for (int t = 0; t < 9; t++)
        #pragma unroll
        for (int e = 0; e < 4; e++) acc[t][e] = 0.f;

    for (int c = 0; c < 8; c++) {
        if (c == 0) CP_WAIT2(); else if (c <= 6) CP_WAIT1(); else CP_WAIT0();
        __syncthreads();   // chunk c ready; buffer (c+2)%3 free for refill
        if (c >= 1 && c <= 5) {
            issue_kv_chunk(sb + R3 + ((c + 2) % 3) * BUFB, kh, kl, s0,
                           (c + 2) * 32, tid);
            CP_COMMIT();
        }

        const uint32_t kb = sb + R3 + (c % 3) * BUFB;
        #pragma unroll
        for (int kk = 0; kk < 32; kk += 16) {
            uint32_t ah[4], al[4];
            uint32_t aoff = (uint32_t)((wm * 16 + aRow) * QSA + c * 32 + kk + aCol) * 2;
            ldsm_x4(ah[0], ah[1], ah[2], ah[3], sb + R2 + aoff);
            ldsm_x4(al[0], al[1], al[2], al[3], sb + R2 + 16896 + aoff);
            uint32_t bh[9][2], bl[9][2];
            #pragma unroll
            for (int t2 = 0; t2 < 4; t2++) {
                uint32_t off = (uint32_t)((wn * 72 + t2 * 16 + bRowE) * KCH +
                                          kk + bColE) * 2;
                ldsm_x4(bh[t2 * 2][0], bh[t2 * 2][1],
                        bh[t2 * 2 + 1][0], bh[t2 * 2 + 1][1], kb + off);
                ldsm_x4(bl[t2 * 2][0], bl[t2 * 2][1],
                        bl[t2 * 2 + 1][0], bl[t2 * 2 + 1][1], kb + HLO + off);
            }
            {
                uint32_t off = (uint32_t)((wn * 72 + 64 + (lane & 7)) * KCH +
                                          kk + bColE) * 2;
                ldsm_x2(bh[8][0], bh[8][1], kb + off);
                ldsm_x2(bl[8][0], bl[8][1], kb + HLO + off);
            }
            #pragma unroll
            for (int t = 0; t < 9; t++) {
                mma_bf16(acc[t], ah, bh[t]);
                mma_bf16(acc[t], ah, bl[t]);
                mma_bf16(acc[t], al, bh[t]);
            }
        }
    }
    __syncthreads();   // all warps done with all K buffers (esp. chunk 7 in buf 1)

    // ---- prefetch V chunks 0..2 (overlaps Ssm stores + softmax) ----
    issue_kv_chunk(sb + R3, vh, vl, s0, 0, tid);             CP_COMMIT();
    issue_kv_chunk(sb + R3 + BUFB, vh, vl, s0, 32, tid);     CP_COMMIT();
    issue_kv_chunk(sb + R3 + 2 * BUFB, vh, vl, s0, 64, tid); CP_COMMIT();

    // store energies to Ssm
    #pragma unroll
    for (int t = 0; t < 9; t++)
        #pragma unroll
        for (int h = 0; h < 2; h++) {
            int row = wm * 16 + (lane >> 2) + h * 8;
            int col = wn * 72 + t * 8 + (lane & 3) * 2;
            *(float2*)&Ssm[row * SST + col] =
                make_float2(acc[t][h * 2], acc[t][h * 2 + 1]);
        }
    __syncthreads();

    // ---- softmax: warp wid owns rows wid*4..wid*4+3; window [i, i+256] ----
    for (int r = 0; r < 4; r++) {
        int i = wid * 4 + r;
        float m = -1e30f;
        for (int j = i + lane; j <= i + 256; j += 32)
            m = fmaxf(m, Ssm[i * SST + j]);
        #pragma unroll
        for (int o = 16; o > 0; o >>= 1)
            m = fmaxf(m, __shfl_xor_sync(0xffffffffu, m, o));
        float l = 0.f;
        for (int j = i + lane; j <= i + 256; j += 32) {
            float e = __expf(Ssm[i * SST + j] - m);
            Ssm[i * SST + j] = e;
            l += e;
        }
        #pragma unroll
        for (int o = 16; o > 0; o >>= 1)
            l += __shfl_xor_sync(0xffffffffu, l, o);
        float inv = 1.f / l;
        for (int j = lane; j < KR; j += 32) {
            float pv = (j >= i && j <= i + 256) ? Ssm[i * SST + j] * inv : 0.f;
            __nv_bfloat16 hi, lo;
            bf16_split(pv, hi, lo);
            Ph[i * PST + j] = hi;
            Pl[i * PST + j] = lo;
        }
    }
    __syncthreads();

    // ---- preload P fragments into registers (once) ----
    uint32_t pH[18][4], pL[18][4];
    #pragma unroll
    for (int kk = 0; kk < 18; kk++) {
        uint32_t off = (uint32_t)((wm * 16 + aRow) * PST + kk * 16 + aCol) * 2;
        ldsm_x4(pH[kk][0], pH[kk][1], pH[kk][2], pH[kk][3], sb + R2 + off);
        ldsm_x4(pL[kk][0], pL[kk][1], pL[kk][2], pL[kk][3], sb + R2 + 18944 + off);
    }

    // ---- Phase 2: O = P @ V, 8 chunks of 32 cols, 1 sync/chunk ----
    for (int c = 0; c < 8; c++) {
        if (c == 0) CP_WAIT2(); else if (c <= 6) CP_WAIT1(); else CP_WAIT0();
        __syncthreads();
        if (c >= 1 && c <= 5) {
            issue_kv_chunk(sb + R3 + ((c + 2) % 3) * BUFB, vh, vl, s0,
                           (c + 2) * 32, tid);
            CP_COMMIT();
        }

        const uint32_t vb = sb + R3 + (c % 3) * BUFB;
        float acc2[4] = {0.f, 0.f, 0.f, 0.f};
        #pragma unroll
        for (int kk = 0; kk < 18; kk++) {
            uint32_t off = (uint32_t)((kk * 16 + (lane & 15)) * KCH + wn * 8) * 2;
            uint32_t bhf[2], blf[2];
            ldsm_x2_t(bhf[0], bhf[1], vb + off);
            ldsm_x2_t(blf[0], blf[1], vb + HLO + off);
            mma_bf16(acc2, pH[kk], bhf);
            mma_bf16(acc2, pH[kk], blf);
            mma_bf16(acc2, pL[kk], bhf);
        }

        #pragma unroll
        for (int h = 0; h < 2; h++) {
            int row = s0 + wm * 16 + (lane >> 2) + h * 8;
            int col = c * 32 + wn * 8 + (lane & 3) * 2;
            *(float2*)&out[((size_t)b * S_LEN + row) * 256 + col] =
                make_float2(acc2[h * 2], acc2[h * 2 + 1]);
        }
    }
}

// ---------------------------------------------------------------------------
extern "C" void kernel_launch(void* const* d_in, const int* in_sizes, int n_in,
                              void* d_out, int out_size)
{
    const float* x  = (const float*)d_in[0];
    const float* Wq = (const float*)d_in[1];
    const float* bq = (const float*)d_in[2];
    const float* Wk = (const float*)d_in[3];
    const float* bk = (const float*)d_in[4];
    const float* Wv = (const float*)d_in[5];
    const float* bv = (const float*)d_in[6];
    float* out = (float*)d_out;

    cudaFuncSetAttribute(qkv_gemm_kernel,
                         cudaFuncAttributeMaxDynamicSharedMemorySize, QKV_SMEM);
    cudaFuncSetAttribute(attn_tc_kernel,
                         cudaFuncAttributeMaxDynamicSharedMemorySize, ATTN_SMEM);

    prep_split_kernel<<<(X4 + 3 * W4 + 255) / 256, 256>>>(x, Wq, Wk, Wv);
    qkv_gemm_kernel<<<dim3(32, 2, 3), 256, QKV_SMEM>>>(bq, bk, bv);
    attn_tc_kernel<<<dim3(S_LEN / TQ, B_SZ), 256, ATTN_SMEM>>>(out);
}

// round 12
// speedup vs baseline: 1.1846x; 1.1846x over previous
#include <cuda_runtime.h>
#include <cuda_bf16.h>
#include <cstdint>

#define B_SZ  2
#define S_LEN 2048
#define E_DIM 256
#define TQ    32          // q rows per attention block
#define KR    288         // k rows per block window
#define SST   292         // Ssm f32 row stride
#define QSA   264         // Q smem halfword stride (528B rows)
#define PST   296         // P smem halfword stride (592B rows)
#define KCH   40          // K/V chunk halfword stride (80B rows)
#define OST   34          // Osm f32 row stride (even -> float2 aligned)

// attn smem layout (bytes)
#define R2    37376       // Q (later P) region; R1 = S/Osm at 0
#define R3    75264       // K/V triple buffers
#define BUFB  46080       // bytes per buffer (hi+lo)
#define HLO   23040       // lo half offset within buffer
#define ATTN_SMEM (R3 + 3 * BUFB)   // 213504

// bf16 hi/lo q,k,v scratch (no cudaMalloc allowed)
__device__ __nv_bfloat16 g_qh[B_SZ * S_LEN * E_DIM];
__device__ __nv_bfloat16 g_ql[B_SZ * S_LEN * E_DIM];
__device__ __nv_bfloat16 g_kh[B_SZ * S_LEN * E_DIM];
__device__ __nv_bfloat16 g_kl[B_SZ * S_LEN * E_DIM];
__device__ __nv_bfloat16 g_vh[B_SZ * S_LEN * E_DIM];
__device__ __nv_bfloat16 g_vl[B_SZ * S_LEN * E_DIM];

// ---------------------------------------------------------------------------
// PTX helpers
// ---------------------------------------------------------------------------
__device__ __forceinline__ uint32_t smem_u32(const void* p) {
    uint32_t a;
    asm("{ .reg .u64 t; cvta.to.shared.u64 t, %1; cvt.u32.u64 %0, t; }"
        : "=r"(a) : "l"(p));
    return a;
}

__device__ __forceinline__ void ldsm_x4(uint32_t& r0, uint32_t& r1,
                                        uint32_t& r2, uint32_t& r3, uint32_t a) {
    asm volatile("ldmatrix.sync.aligned.m8n8.x4.shared.b16 {%0,%1,%2,%3}, [%4];"
                 : "=r"(r0), "=r"(r1), "=r"(r2), "=r"(r3) : "r"(a));
}

__device__ __forceinline__ void ldsm_x2(uint32_t& r0, uint32_t& r1, uint32_t a) {
    asm volatile("ldmatrix.sync.aligned.m8n8.x2.shared.b16 {%0,%1}, [%2];"
                 : "=r"(r0), "=r"(r1) : "r"(a));
}

__device__ __forceinline__ void ldsm_x2_t(uint32_t& r0, uint32_t& r1, uint32_t a) {
    asm volatile("ldmatrix.sync.aligned.m8n8.x2.trans.shared.b16 {%0,%1}, [%2];"
                 : "=r"(r0), "=r"(r1) : "r"(a));
}

__device__ __forceinline__ void mma_bf16(float* d, const uint32_t* a,
                                         const uint32_t* b) {
    asm volatile(
        "mma.sync.aligned.m16n8k16.row.col.f32.bf16.bf16.f32 "
        "{%0,%1,%2,%3}, {%4,%5,%6,%7}, {%8,%9}, {%0,%1,%2,%3};"
        : "+f"(d[0]), "+f"(d[1]), "+f"(d[2]), "+f"(d[3])
        : "r"(a[0]), "r"(a[1]), "r"(a[2]), "r"(a[3]), "r"(b[0]), "r"(b[1]));
}

__device__ __forceinline__ void bf16_split(float x, __nv_bfloat16& hi,
                                           __nv_bfloat16& lo) {
    hi = __float2bfloat16_rn(x);
    lo = __float2bfloat16_rn(x - __bfloat162float(hi));
}

__device__ __forceinline__ void cp16(uint32_t dst, const void* src, int srcsize) {
    asm volatile("cp.async.cg.shared.global [%0], [%1], 16, %2;"
                 :: "r"(dst), "l"(src), "r"(srcsize) : "memory");
}
#define CP_COMMIT() asm volatile("cp.async.commit_group;" ::: "memory")
#define CP_WAIT0()  asm volatile("cp.async.wait_group 0;" ::: "memory")
#define CP_WAIT1()  asm volatile("cp.async.wait_group 1;" ::: "memory")
#define CP_WAIT2()  asm volatile("cp.async.wait_group 2;" ::: "memory")

// ---------------------------------------------------------------------------
// Kernel 1: QKV projection (R6 version — measured fastest at 25.8us).
// C = X @ W^T + b, CTA tile M=128 N=128 K=256 (BK=32), grid (32,2,3).
// ---------------------------------------------------------------------------
#define QST 40   // 80B rows: 16B-aligned, conflict-free

__global__ __launch_bounds__(256) void qkv_tc_kernel(
    const float* __restrict__ x,
    const float* __restrict__ Wq, const float* __restrict__ bq,
    const float* __restrict__ Wk, const float* __restrict__ bk,
    const float* __restrict__ Wv, const float* __restrict__ bv)
{
    __shared__ __align__(16) __nv_bfloat16 sAhi[128 * QST];
    __shared__ __align__(16) __nv_bfloat16 sAlo[128 * QST];
    __shared__ __align__(16) __nv_bfloat16 sBhi[128 * QST];
    __shared__ __align__(16) __nv_bfloat16 sBlo[128 * QST];

    const int z = blockIdx.z;
    const float* __restrict__ W    = (z == 0) ? Wq : (z == 1) ? Wk : Wv;
    const float* __restrict__ bias = (z == 0) ? bq : (z == 1) ? bk : bv;
    __nv_bfloat16* __restrict__ Ch = (z == 0) ? g_qh : (z == 1) ? g_kh : g_vh;
    __nv_bfloat16* __restrict__ Cl = (z == 0) ? g_ql : (z == 1) ? g_kl : g_vl;

    const int m0 = blockIdx.x * 128;
    const int n0 = blockIdx.y * 128;
    const int tid  = threadIdx.x;
    const int wid  = tid >> 5;
    const int lane = tid & 31;
    const int wm   = wid >> 2;
    const int wn   = wid & 3;

    const uint32_t uAhi = smem_u32(sAhi);
    const uint32_t uAlo = smem_u32(sAlo);
    const uint32_t uBhi = smem_u32(sBhi);
    const uint32_t uBlo = smem_u32(sBlo);

    float acc[4][4][4];
    #pragma unroll
    for (int i = 0; i < 4; i++)
        #pragma unroll
        for (int j = 0; j < 4; j++)
            #pragma unroll
            for (int e = 0; e < 4; e++) acc[i][j][e] = 0.f;

    const int aRow = (lane & 15);
    const int aCol = (lane >> 4) * 8;
    const int l15  = lane & 15;
    const int bRow = (l15 & 7);
    const int bCol = (l15 >> 3) * 8;

    for (int c = 0; c < 8; c++) {
        const int kc = c * 32;
        __syncthreads();
        #pragma unroll
        for (int p = 0; p < 4; p++) {
            int i4  = tid + p * 256;
            int row = i4 >> 3;
            int c4  = (i4 & 7) * 4;
            float4 v = *(const float4*)&x[(size_t)(m0 + row) * 256 + kc + c4];
            __nv_bfloat16 h0, l0, h1, l1, h2, l2, h3, l3;
            bf16_split(v.x, h0, l0); bf16_split(v.y, h1, l1);
            bf16_split(v.z, h2, l2); bf16_split(v.w, h3, l3);
            __nv_bfloat162* ph = (__nv_bfloat162*)&sAhi[row * QST + c4];
            __nv_bfloat162* pl = (__nv_bfloat162*)&sAlo[row * QST + c4];
            ph[0] = __nv_bfloat162(h0, h1); ph[1] = __nv_bfloat162(h2, h3);
            pl[0] = __nv_bfloat162(l0, l1); pl[1] = __nv_bfloat162(l2, l3);

            v = *(const float4*)&W[(size_t)(n0 + row) * 256 + kc + c4];
            bf16_split(v.x, h0, l0); bf16_split(v.y, h1, l1);
            bf16_split(v.z, h2, l2); bf16_split(v.w, h3, l3);
            ph = (__nv_bfloat162*)&sBhi[row * QST + c4];
            pl = (__nv_bfloat162*)&sBlo[row * QST + c4];
            ph[0] = __nv_bfloat162(h0, h1); ph[1] = __nv_bfloat162(h2, h3);
            pl[0] = __nv_bfloat162(l0, l1); pl[1] = __nv_bfloat162(l2, l3);
        }
        __syncthreads();

        #pragma unroll
        for (int kk = 0; kk < 32; kk += 16) {
            uint32_t ah[4][4], al[4][4], bh[4][2], bl[4][2];
            #pragma unroll
            for (int mi = 0; mi < 4; mi++) {
                uint32_t off = (uint32_t)((wm * 64 + mi * 16 + aRow) * QST +
                                          kk + aCol) * 2;
                ldsm_x4(ah[mi][0], ah[mi][1], ah[mi][2], ah[mi][3], uAhi + off);
                ldsm_x4(al[mi][0], al[mi][1], al[mi][2], al[mi][3], uAlo + off);
            }
            #pragma unroll
            for (int nj = 0; nj < 4; nj++) {
                uint32_t off = (uint32_t)((wn * 32 + nj * 8 + bRow) * QST +
                                          kk + bCol) * 2;
                ldsm_x2(bh[nj][0], bh[nj][1], uBhi + off);
                ldsm_x2(bl[nj][0], bl[nj][1], uBlo + off);
            }
            #pragma unroll
            for (int mi = 0; mi < 4; mi++)
                #pragma unroll
                for (int nj = 0; nj < 4; nj++) {
                    mma_bf16(acc[mi][nj], ah[mi], bh[nj]);
                    mma_bf16(acc[mi][nj], ah[mi], bl[nj]);
                    mma_bf16(acc[mi][nj], al[mi], bh[nj]);
                }
        }
    }

    // epilogue: add bias, split to bf16 hi/lo, store
    #pragma unroll
    for (int mi = 0; mi < 4; mi++) {
        int r0 = m0 + wm * 64 + mi * 16 + (lane >> 2);
        #pragma unroll
        for (int nj = 0; nj < 4; nj++) {
            int col = n0 + wn * 32 + nj * 8 + (lane & 3) * 2;
            float2 bv2 = *(const float2*)&bias[col];
            #pragma unroll
            for (int h = 0; h < 2; h++) {
                int row = r0 + h * 8;
                float cx = acc[mi][nj][h * 2 + 0] + bv2.x;
                float cy = acc[mi][nj][h * 2 + 1] + bv2.y;
                __nv_bfloat16 hx, lx, hy, ly;
                bf16_split(cx, hx, lx);
                bf16_split(cy, hy, ly);
                *(__nv_bfloat162*)&Ch[(size_t)row * 256 + col] = __nv_bfloat162(hx, hy);
                *(__nv_bfloat162*)&Cl[(size_t)row * 256 + col] = __nv_bfloat162(lx, ly);
            }
        }
    }
}

// ---------------------------------------------------------------------------
// attn helper: async chunk issuance (512 threads)
// ---------------------------------------------------------------------------
__device__ __forceinline__ void issue_kv_chunk(
    uint32_t dst_base, const __nv_bfloat16* __restrict__ hi,
    const __nv_bfloat16* __restrict__ lo, int s0, int colbase, int tid)
{
    #pragma unroll
    for (int p = 0; p < 5; p++) {
        int idx = tid + p * 512;               // 0..2559, need < 2304
        if (idx < 2304) {
            int half = idx >= 1152;
            int u    = half ? idx - 1152 : idx;
            int r    = u >> 2;                 // 0..287
            int seg  = u & 3;                  // 16B segment
            int g    = s0 - 128 + r;
            bool ok  = (unsigned)g < S_LEN;
            const __nv_bfloat16* src =
                (half ? lo : hi) + (size_t)(ok ? g : 0) * 256 + colbase + seg * 8;
            uint32_t dst = dst_base + half * HLO + r * 80 + seg * 16;
            cp16(dst, src, ok ? 16 : 0);
        }
    }
}

// ---------------------------------------------------------------------------
// Kernel 2: banded attention, 512 threads (16 warps), K-split warp groups.
// Group g = wid>>3 handles half the contraction dim in both GEMM phases;
// partials reduced through smem. cp.async triple-buffer as in R9.
// ---------------------------------------------------------------------------
__global__ __launch_bounds__(512) void attn_tc_kernel(float* __restrict__ out)
{
    extern __shared__ char smem[];
    const uint32_t sb = smem_u32(smem);
    float* Ssm = (float*)smem;
    float* Osm = (float*)smem;                      // reuses dead S region
    __nv_bfloat16* Ph = (__nv_bfloat16*)(smem + R2);
    __nv_bfloat16* Pl = (__nv_bfloat16*)(smem + R2 + 18944);

    const int b    = blockIdx.y;
    const int s0   = blockIdx.x * TQ;
    const int tid  = threadIdx.x;
    const int wid  = tid >> 5;       // 0..15
    const int lane = tid & 31;
    const int grp  = wid >> 3;       // 0..1 k-split group
    const int w8   = wid & 7;
    const int wm   = w8 >> 2;        // 0..1 -> 16-row half
    const int wn   = w8 & 3;         // 0..3

    const size_t boff = (size_t)b * S_LEN * E_DIM;
    const __nv_bfloat16* __restrict__ qh = g_qh + boff;
    const __nv_bfloat16* __restrict__ ql = g_ql + boff;
    const __nv_bfloat16* __restrict__ kh = g_kh + boff;
    const __nv_bfloat16* __restrict__ kl = g_kl + boff;
    const __nv_bfloat16* __restrict__ vh = g_vh + boff;
    const __nv_bfloat16* __restrict__ vl = g_vl + boff;

    const int aRow  = lane & 15;
    const int aCol  = (lane >> 4) * 8;
    const int bRowE = (lane & 7) + ((lane >> 4) << 3);
    const int bColE = ((lane >> 3) & 1) * 8;

    // ---- prologue: async Q (group 0 with K0) + K chunks 0..2 ----
    #pragma unroll
    for (int p = 0; p < 4; p++) {
        int idx  = tid + p * 512;              // 0..2047
        int half = idx >> 10;
        int rem  = idx & 1023;
        int r    = rem >> 5;                   // 0..31
        int seg  = rem & 31;
        const __nv_bfloat16* src =
            (half ? ql : qh) + (size_t)(s0 + r) * 256 + seg * 8;
        cp16(sb + R2 + half * 16896 + r * 528 + seg * 16, src, 16);
    }
    issue_kv_chunk(sb + R3, kh, kl, s0, 0, tid);             CP_COMMIT();
    issue_kv_chunk(sb + R3 + BUFB, kh, kl, s0, 32, tid);     CP_COMMIT();
    issue_kv_chunk(sb + R3 + 2 * BUFB, kh, kl, s0, 64, tid); CP_COMMIT();

    // ---- Phase 1: S[32][288] = Q @ K^T; group g does kk = g*16 per chunk ----
    float acc[9][4];
    #pragma unroll
    for (int t = 0; t < 9; t++)
        #pragma unroll
        for (int e = 0; e < 4; e++) acc[t][e] = 0.f;

    const int kk1 = grp * 16;
    for (int c = 0; c < 8; c++) {
        if (c == 0) CP_WAIT2(); else if (c <= 6) CP_WAIT1(); else CP_WAIT0();
        __syncthreads();   // chunk c ready; buffer (c+2)%3 free for refill
        if (c >= 1 && c <= 5) {
            issue_kv_chunk(sb + R3 + ((c + 2) % 3) * BUFB, kh, kl, s0,
                           (c + 2) * 32, tid);
            CP_COMMIT();
        }

        const uint32_t kb = sb + R3 + (c % 3) * BUFB;
        uint32_t ah[4], al[4];
        {
            uint32_t aoff = (uint32_t)((wm * 16 + aRow) * QSA + c * 32 + kk1 + aCol) * 2;
            ldsm_x4(ah[0], ah[1], ah[2], ah[3], sb + R2 + aoff);
            ldsm_x4(al[0], al[1], al[2], al[3], sb + R2 + 16896 + aoff);
        }
        #pragma unroll
        for (int t2 = 0; t2 < 4; t2++) {
            uint32_t off = (uint32_t)((wn * 72 + t2 * 16 + bRowE) * KCH +
                                      kk1 + bColE) * 2;
            uint32_t bh0, bh1, bh2, bh3, bl0, bl1, bl2, bl3;
            ldsm_x4(bh0, bh1, bh2, bh3, kb + off);
            ldsm_x4(bl0, bl1, bl2, bl3, kb + HLO + off);
            uint32_t bhA[2] = {bh0, bh1}, bhB[2] = {bh2, bh3};
            uint32_t blA[2] = {bl0, bl1}, blB[2] = {bl2, bl3};
            mma_bf16(acc[t2 * 2], ah, bhA);
            mma_bf16(acc[t2 * 2], ah, blA);
            mma_bf16(acc[t2 * 2], al, bhA);
            mma_bf16(acc[t2 * 2 + 1], ah, bhB);
            mma_bf16(acc[t2 * 2 + 1], ah, blB);
            mma_bf16(acc[t2 * 2 + 1], al, bhB);
        }
        {
            uint32_t off = (uint32_t)((wn * 72 + 64 + (lane & 7)) * KCH +
                                      kk1 + bColE) * 2;
            uint32_t bh[2], bl[2];
            ldsm_x2(bh[0], bh[1], kb + off);
            ldsm_x2(bl[0], bl[1], kb + HLO + off);
            mma_bf16(acc[8], ah, bh);
            mma_bf16(acc[8], ah, bl);
            mma_bf16(acc[8], al, bh);
        }
    }
    __syncthreads();   // all K-buffer reads done

    // ---- prefetch V chunks 0..2 (overlaps reduce + softmax) ----
    issue_kv_chunk(sb + R3, vh, vl, s0, 0, tid);             CP_COMMIT();
    issue_kv_chunk(sb + R3 + BUFB, vh, vl, s0, 32, tid);     CP_COMMIT();
    issue_kv_chunk(sb + R3 + 2 * BUFB, vh, vl, s0, 64, tid); CP_COMMIT();

    // ---- reduce partial energies: grp0 stores, grp1 adds ----
    if (grp == 0) {
        #pragma unroll
        for (int t = 0; t < 9; t++)
            #pragma unroll
            for (int h = 0; h < 2; h++) {
                int row = wm * 16 + (lane >> 2) + h * 8;
                int col = wn * 72 + t * 8 + (lane & 3) * 2;
                *(float2*)&Ssm[row * SST + col] =
                    make_float2(acc[t][h * 2], acc[t][h * 2 + 1]);
            }
    }
    __syncthreads();
    if (grp == 1) {
        #pragma unroll
        for (int t = 0; t < 9; t++)
            #pragma unroll
            for (int h = 0; h < 2; h++) {
                int row = wm * 16 + (lane >> 2) + h * 8;
                int col = wn * 72 + t * 8 + (lane & 3) * 2;
                float2 s = *(float2*)&Ssm[row * SST + col];
                s.x += acc[t][h * 2];
                s.y += acc[t][h * 2 + 1];
                *(float2*)&Ssm[row * SST + col] = s;
            }
    }
    __syncthreads();

    // ---- softmax: warp wid owns rows wid*2, wid*2+1; window [i, i+256] ----
    for (int r = 0; r < 2; r++) {
        int i = wid * 2 + r;
        float m = -1e30f;
        for (int j = i + lane; j <= i + 256; j += 32)
            m = fmaxf(m, Ssm[i * SST + j]);
        #pragma unroll
        for (int o = 16; o > 0; o >>= 1)
            m = fmaxf(m, __shfl_xor_sync(0xffffffffu, m, o));
        float l = 0.f;
        for (int j = i + lane; j <= i + 256; j += 32) {
            float e = __expf(Ssm[i * SST + j] - m);
            Ssm[i * SST + j] = e;
            l += e;
        }
        #pragma unroll
        for (int o = 16; o > 0; o >>= 1)
            l += __shfl_xor_sync(0xffffffffu, l, o);
        float inv = 1.f / l;
        for (int j = lane; j < KR; j += 32) {
            float pv = (j >= i && j <= i + 256) ? Ssm[i * SST + j] * inv : 0.f;
            __nv_bfloat16 hi, lo;
            bf16_split(pv, hi, lo);
            Ph[i * PST + j] = hi;
            Pl[i * PST + j] = lo;
        }
    }
    __syncthreads();

    // ---- preload P fragments for this group's k-rows (kk 9g .. 9g+8) ----
    uint32_t pH[9][4], pL[9][4];
    #pragma unroll
    for (int j = 0; j < 9; j++) {
        int kkabs = grp * 9 + j;
        uint32_t off = (uint32_t)((wm * 16 + aRow) * PST + kkabs * 16 + aCol) * 2;
        ldsm_x4(pH[j][0], pH[j][1], pH[j][2], pH[j][3], sb + R2 + off);
        ldsm_x4(pL[j][0], pL[j][1], pL[j][2], pL[j][3], sb + R2 + 18944 + off);
    }

    // ---- Phase 2: O = P @ V; group g handles V rows [144g, 144g+144) ----
    for (int c = 0; c < 8; c++) {
        if (c == 0) CP_WAIT2(); else if (c <= 6) CP_WAIT1(); else CP_WAIT0();
        __syncthreads();   // V chunk c ready; Osm from prev chunk consumed
        if (c >= 1 && c <= 5) {
            issue_kv_chunk(sb + R3 + ((c + 2) % 3) * BUFB, vh, vl, s0,
                           (c + 2) * 32, tid);
            CP_COMMIT();
        }

        const uint32_t vb = sb + R3 + (c % 3) * BUFB;
        float acc2[4] = {0.f, 0.f, 0.f, 0.f};
        #pragma unroll
        for (int j = 0; j < 9; j++) {
            int kkabs = grp * 9 + j;
            uint32_t off = (uint32_t)((kkabs * 16 + (lane & 15)) * KCH + wn * 8) * 2;
            uint32_t bhf[2], blf[2];
            ldsm_x2_t(bhf[0], bhf[1], vb + off);
            ldsm_x2_t(blf[0], blf[1], vb + HLO + off);
            mma_bf16(acc2, pH[j], bhf);
            mma_bf16(acc2, pH[j], blf);
            mma_bf16(acc2, pL[j], bhf);
        }

        if (grp == 0) {
            #pragma unroll
            for (int h = 0; h < 2; h++) {
                int row = wm * 16 + (lane >> 2) + h * 8;
                int col = wn * 8 + (lane & 3) * 2;
                *(float2*)&Osm[row * OST + col] =
                    make_float2(acc2[h * 2], acc2[h * 2 + 1]);
            }
        }
        __syncthreads();
        if (grp == 1) {
            #pragma unroll
            for (int h = 0; h < 2; h++) {
                int row = wm * 16 + (lane >> 2) + h * 8;
                int col = wn * 8 + (lane & 3) * 2;
                float2 s = *(float2*)&Osm[row * OST + col];
                s.x += acc2[h * 2];
                s.y += acc2[h * 2 + 1];
                *(float2*)&out[((size_t)b * S_LEN + s0 + row) * 256 +
                               c * 32 + col] = s;
            }
        }
    }
}

// ---------------------------------------------------------------------------
extern "C" void kernel_launch(void* const* d_in, const int* in_sizes, int n_in,
                              void* d_out, int out_size)
{
    const float* x  = (const float*)d_in[0];
    const float* Wq = (const float*)d_in[1];
    const float* bq = (const float*)d_in[2];
    const float* Wk = (const float*)d_in[3];
    const float* bk = (const float*)d_in[4];
    const float* Wv = (const float*)d_in[5];
    const float* bv = (const float*)d_in[6];
    float* out = (float*)d_out;

    cudaFuncSetAttribute(attn_tc_kernel,
                         cudaFuncAttributeMaxDynamicSharedMemorySize, ATTN_SMEM);

    qkv_tc_kernel<<<dim3(32, 2, 3), 256>>>(x, Wq, bq, Wk, bk, Wv, bv);
    attn_tc_kernel<<<dim3(S_LEN / TQ, B_SZ), 512, ATTN_SMEM>>>(out);
}